// round 3
// baseline (speedup 1.0000x reference)
#include <cuda_runtime.h>
#include <math.h>

#define NN 8192
#define EE 131072
#define DIM 32
#define HID 128
#define BG 64
#define NMP 3
#define S2S 3
#define KDIM 4096   // HID*DIM

typedef unsigned long long ull;

__device__ __forceinline__ ull pk2(float lo, float hi) {
    ull r; asm("mov.b64 %0,{%1,%2};" : "=l"(r) : "f"(lo), "f"(hi)); return r;
}
__device__ __forceinline__ float2 upk2(ull v) {
    float2 r; asm("mov.b64 {%0,%1},%2;" : "=f"(r.x), "=f"(r.y) : "l"(v)); return r;
}
__device__ __forceinline__ ull ffma2(ull a, ull b, ull c) {
    ull d; asm("fma.rn.f32x2 %0,%1,%2,%3;" : "=l"(d) : "l"(a), "l"(b), "l"(c)); return d;
}

// ---------------- scratch (device globals; no allocation) ----------------
__device__ float g_out[NN * DIM];          // node features (out == GRU hidden h)
__device__ float g_h[EE * HID];            // edge MLP hidden                  67MB
__device__ float g_P[(size_t)NN * KDIM];   // per-node accumulated outer prods 134MB
__device__ float g_usum[NN * DIM];
__device__ float g_aggpre[NN * DIM];
__device__ int   g_cnt[NN];
__device__ int   g_rowptr[NN + 1];
__device__ int   g_woff[NN];
__device__ int   g_eids[EE];
__device__ float g_deg[NN];
__device__ int   g_gptr[BG + 1];
__device__ float g_qh[BG * DIM];
__device__ float g_qc[BG * DIM];
__device__ float g_qstar[BG * 2 * DIM];

__device__ __forceinline__ float sigm(float x) { return 1.0f / (1.0f + expf(-x)); }

// ---------------- init / setup kernels ----------------
__global__ void k_zero_cnt() {
    int i = blockIdx.x * blockDim.x + threadIdx.x;
    if (i < NN) g_cnt[i] = 0;
}

__global__ void k_zero_s2s() {
    int i = blockIdx.x * blockDim.x + threadIdx.x;
    if (i < BG * DIM) { g_qh[i] = 0.f; g_qc[i] = 0.f; }
    if (i < BG * 2 * DIM) g_qstar[i] = 0.f;
}

__global__ void k_init_nodes(const float* __restrict__ x,
                             const float* __restrict__ w0,
                             const float* __restrict__ b0) {
    int idx = blockIdx.x * blockDim.x + threadIdx.x;
    if (idx >= NN * DIM) return;
    int n = idx >> 5, j = idx & 31;
    float v = x[n] * w0[j] + b0[j];
    g_out[idx] = v > 0.f ? v : 0.f;
}

__global__ void k_edge_hidden(const float* __restrict__ ea,
                              const float* __restrict__ w1,
                              const float* __restrict__ b1) {
    int idx = blockIdx.x * blockDim.x + threadIdx.x;
    if (idx >= EE * HID) return;
    int e = idx >> 7, k = idx & 127;
    float v = ea[2 * e] * __ldg(&w1[k]) + ea[2 * e + 1] * __ldg(&w1[HID + k]) + __ldg(&b1[k]);
    g_h[idx] = v > 0.f ? v : 0.f;
}

__global__ void k_count(const int* __restrict__ ei) {
    int e = blockIdx.x * blockDim.x + threadIdx.x;
    if (e < EE) atomicAdd(&g_cnt[ei[EE + e]], 1);
}

// single-block exclusive scan of g_cnt (8192) -> rowptr, woff, deg
__global__ void k_scan() {
    __shared__ int tot[1024];
    int t = threadIdx.x;
    int base = t * 8;
    int v[8]; int s = 0;
#pragma unroll
    for (int i = 0; i < 8; i++) { v[i] = g_cnt[base + i]; s += v[i]; }
    tot[t] = s;
    __syncthreads();
    for (int d = 1; d < 1024; d <<= 1) {
        int add = (t >= d) ? tot[t - d] : 0;
        __syncthreads();
        tot[t] += add;
        __syncthreads();
    }
    int run = tot[t] - s;
#pragma unroll
    for (int i = 0; i < 8; i++) {
        g_rowptr[base + i] = run;
        g_woff[base + i] = run;
        g_deg[base + i] = (float)(v[i] > 0 ? v[i] : 1);
        run += v[i];
    }
    if (t == 1023) g_rowptr[NN] = run;
}

__global__ void k_fill(const int* __restrict__ ei) {
    int e = blockIdx.x * blockDim.x + threadIdx.x;
    if (e >= EE) return;
    int dst = ei[EE + e];
    int pos = atomicAdd(&g_woff[dst], 1);
    g_eids[pos] = e;
}

__global__ void k_gptr(const int* __restrict__ batch) {
    int b = threadIdx.x;
    if (b > BG) return;
    int lo = 0, hi = NN;
    while (lo < hi) {
        int mid = (lo + hi) >> 1;
        if (batch[mid] < b) lo = mid + 1; else hi = mid;
    }
    g_gptr[b] = lo;
}

// ---------------- message passing ----------------
// one block (128 thr) per dst node. Thread (w=warp, l=lane) owns
// k in {l, l+32, l+64, l+96} and d in [8w, 8w+8).
// P[n,k,d] += h_e[k] * u_src[d], accumulated in f32x2 packs.
__global__ void k_scatter(const int* __restrict__ ei) {
    __shared__ float sh[8][HID];   // staged h for 8 edges
    __shared__ float su[8][DIM];   // staged u for 8 edges
    __shared__ int   se[8];
    int n = blockIdx.x;
    int tid = threadIdx.x;
    int w = tid >> 5;        // 0..3  (d-group)
    int l = tid & 31;        // 0..31 (k base)
    int lo = g_rowptr[n], hi = g_rowptr[n + 1];

    ull acc[4][4];
#pragma unroll
    for (int j = 0; j < 4; j++)
#pragma unroll
        for (int q = 0; q < 4; q++) acc[j][q] = 0ull;
    float us = 0.f;

    for (int base = lo; base < hi; base += 8) {
        int m = hi - base; if (m > 8) m = 8;
        __syncthreads();
        if (tid < m) se[tid] = g_eids[base + tid];
        __syncthreads();
        // stage u: warp w handles edges w, w+4 (coalesced 128B per edge)
        for (int e = w; e < m; e += 4) su[e][l] = g_out[ei[se[e]] * DIM + l];
        // stage h: all 128 threads load one float per edge (coalesced 512B)
        for (int e = 0; e < m; e++) sh[e][tid] = g_h[(size_t)se[e] * HID + tid];
        __syncthreads();
        for (int e = 0; e < m; e++) {
            float h0 = sh[e][l];
            float h1 = sh[e][l + 32];
            float h2 = sh[e][l + 64];
            float h3 = sh[e][l + 96];
            ull hp[4] = { pk2(h0, h0), pk2(h1, h1), pk2(h2, h2), pk2(h3, h3) };
            // u packs: warp-uniform LDS.128 x2 (16B broadcast each)
            const ull* up = (const ull*)&su[e][8 * w];
            ull u0 = up[0], u1 = up[1], u2 = up[2], u3 = up[3];
#pragma unroll
            for (int j = 0; j < 4; j++) {
                acc[j][0] = ffma2(hp[j], u0, acc[j][0]);
                acc[j][1] = ffma2(hp[j], u1, acc[j][1]);
                acc[j][2] = ffma2(hp[j], u2, acc[j][2]);
                acc[j][3] = ffma2(hp[j], u3, acc[j][3]);
            }
            if (w == 0) us += su[e][l];
        }
    }

    float* Pn = g_P + (size_t)n * KDIM;
#pragma unroll
    for (int j = 0; j < 4; j++) {
        int k = l + 32 * j;
#pragma unroll
        for (int q = 0; q < 4; q++) {
            *(float2*)&Pn[k * DIM + 8 * w + 2 * q] = upk2(acc[j][q]);
        }
    }
    if (w == 0) g_usum[n * DIM + l] = us;
}

// aggpre[N,32] = P[N,4096] @ w2flat[4096,32]   (w2 viewed flat: row r=(k*32+d))
// grid = NN/64 = 128 blocks, 256 threads. Tile 64 rows x 32 cols, BK=32.
// thread: rg = tid>>3 (rows 2rg,2rg+1), cg = tid&7 (cols 4cg..4cg+3)
__global__ void k_gemm(const float* __restrict__ w2) {
    __shared__ float As[64][36];   // [row][k], stride 36 (16B aligned, cf-free)
    __shared__ float Bs[32][36];   // [k][col]
    int tid = threadIdx.x;
    int tile = blockIdx.x;
    int rg = tid >> 3;
    int cg = tid & 7;
    ull acc00 = 0, acc01 = 0, acc10 = 0, acc11 = 0;

    const float* Pbase = g_P + (size_t)(tile * 64) * KDIM;
    for (int kc = 0; kc < KDIM; kc += 32) {
        // stage As: 64x32 floats = 512 float4 slots / 256 threads = 2 each
#pragma unroll
        for (int i = 0; i < 2; i++) {
            int s = i * 256 + tid;          // 0..511
            int r = s >> 3, kq = s & 7;     // row, float4-slot within 32
            float4 v = *(const float4*)&Pbase[(size_t)r * KDIM + kc + kq * 4];
            *(float4*)&As[r][kq * 4] = v;
        }
        // stage Bs: 32x32 floats = 256 float4 slots / 256 threads = 1 each
        {
            int kr = tid >> 3, cq = tid & 7;
            float4 v = *(const float4*)&w2[(size_t)(kc + kr) * 32 + cq * 4];
            *(float4*)&Bs[kr][cq * 4] = v;
        }
        __syncthreads();
#pragma unroll
        for (int k = 0; k < 32; k++) {
            float a0 = As[2 * rg][k];
            float a1 = As[2 * rg + 1][k];
            ull ap0 = pk2(a0, a0);
            ull ap1 = pk2(a1, a1);
            const ull* bp = (const ull*)&Bs[k][4 * cg];
            ull b0 = bp[0], b1 = bp[1];
            acc00 = ffma2(ap0, b0, acc00);
            acc01 = ffma2(ap0, b1, acc01);
            acc10 = ffma2(ap1, b0, acc10);
            acc11 = ffma2(ap1, b1, acc11);
        }
        __syncthreads();
    }
    int n0 = tile * 64 + 2 * rg;
    *(float2*)&g_aggpre[n0 * DIM + 4 * cg] = upk2(acc00);
    *(float2*)&g_aggpre[n0 * DIM + 4 * cg + 2] = upk2(acc01);
    *(float2*)&g_aggpre[(n0 + 1) * DIM + 4 * cg] = upk2(acc10);
    *(float2*)&g_aggpre[(n0 + 1) * DIM + 4 * cg + 2] = upk2(acc11);
}

// per-node: agg=(aggpre + usum@B2)/deg ; m=relu(agg + out@root + cb) ; GRU update
__global__ void k_update(const float* __restrict__ b2,
                         const float* __restrict__ rootw,
                         const float* __restrict__ convb,
                         const float* __restrict__ wih,
                         const float* __restrict__ whh,
                         const float* __restrict__ bih,
                         const float* __restrict__ bhh) {
    __shared__ float Msm[8][DIM];
    int n = blockIdx.x * 8 + (threadIdx.x >> 5);
    int o = threadIdx.x & 31;
    int nl = threadIdx.x >> 5;

    float ub = 0.f;
#pragma unroll
    for (int d = 0; d < DIM; d++) ub += g_usum[n * DIM + d] * __ldg(&b2[d * DIM + o]);
    float agg = (g_aggpre[n * DIM + o] + ub) / g_deg[n];
    float mo = agg + __ldg(&convb[o]);
#pragma unroll
    for (int d = 0; d < DIM; d++) mo += g_out[n * DIM + d] * __ldg(&rootw[d * DIM + o]);
    mo = mo > 0.f ? mo : 0.f;
    Msm[nl][o] = mo;
    __syncthreads();

    float ir = __ldg(&bih[o]), iz = __ldg(&bih[32 + o]), inn = __ldg(&bih[64 + o]);
    float hr = __ldg(&bhh[o]), hz = __ldg(&bhh[32 + o]), hn = __ldg(&bhh[64 + o]);
#pragma unroll
    for (int d = 0; d < DIM; d++) {
        float md = Msm[nl][d];
        float hd = g_out[n * DIM + d];
        ir += md * __ldg(&wih[d * 96 + o]);
        iz += md * __ldg(&wih[d * 96 + 32 + o]);
        inn += md * __ldg(&wih[d * 96 + 64 + o]);
        hr += hd * __ldg(&whh[d * 96 + o]);
        hz += hd * __ldg(&whh[d * 96 + 32 + o]);
        hn += hd * __ldg(&whh[d * 96 + 64 + o]);
    }
    float r = sigm(ir + hr);
    float z = sigm(iz + hz);
    float nv = tanhf(inn + r * hn);
    float hold = g_out[n * DIM + o];
    float hnew = (1.f - z) * nv + z * hold;
    __syncwarp();
    g_out[n * DIM + o] = hnew;
}

// ---------------- Set2Set ----------------
__global__ void k_lstm(const float* __restrict__ wih,
                       const float* __restrict__ whh,
                       const float* __restrict__ bih,
                       const float* __restrict__ bhh) {
    __shared__ float gs[128];
    int b = blockIdx.x;
    int j = threadIdx.x;
    float g = __ldg(&bih[j]) + __ldg(&bhh[j]);
#pragma unroll
    for (int t = 0; t < 2 * DIM; t++) g += g_qstar[b * 2 * DIM + t] * __ldg(&wih[t * 128 + j]);
#pragma unroll
    for (int t = 0; t < DIM; t++) g += g_qh[b * DIM + t] * __ldg(&whh[t * 128 + j]);
    gs[j] = g;
    __syncthreads();
    if (j < 32) {
        float i_ = gs[j], f_ = gs[32 + j], gg = gs[64 + j], oo = gs[96 + j];
        float qc = sigm(f_) * g_qc[b * DIM + j] + sigm(i_) * tanhf(gg);
        g_qc[b * DIM + j] = qc;
        g_qh[b * DIM + j] = sigm(oo) * tanhf(qc);
    }
}

__global__ void k_attend() {
    __shared__ float sqh[32];
    __shared__ float ebuf[4096];
    __shared__ float wred[8];
    __shared__ float rpart[8][32];
    __shared__ float s_bmax, s_den;
    int b = blockIdx.x;
    int tid = threadIdx.x;
    int w = tid >> 5, lane = tid & 31;
    int lo = g_gptr[b], hi = g_gptr[b + 1];
    int cnt = hi - lo;
    if (tid < 32) sqh[tid] = g_qh[b * DIM + tid];
    __syncthreads();

    float mymax = -1e30f;
    for (int i = lo + w; i < hi; i += 8) {
        float v = g_out[(size_t)i * DIM + lane] * sqh[lane];
#pragma unroll
        for (int off = 16; off; off >>= 1) v += __shfl_xor_sync(0xffffffffu, v, off);
        if (lane == 0) ebuf[i - lo] = v;
        mymax = fmaxf(mymax, v);
    }
    if (lane == 0) wred[w] = mymax;
    __syncthreads();
    if (tid == 0) {
        float m = -1e30f;
        for (int q = 0; q < 8; q++) m = fmaxf(m, wred[q]);
        s_bmax = m;
    }
    __syncthreads();
    float bm = s_bmax;

    float s = 0.f;
    for (int idx = tid; idx < cnt; idx += 256) {
        float ev = expf(ebuf[idx] - bm);
        ebuf[idx] = ev;
        s += ev;
    }
#pragma unroll
    for (int off = 16; off; off >>= 1) s += __shfl_xor_sync(0xffffffffu, s, off);
    if (lane == 0) wred[w] = s;
    __syncthreads();
    if (tid == 0) {
        float t = 0.f;
        for (int q = 0; q < 8; q++) t += wred[q];
        s_den = t;
    }
    __syncthreads();
    float invden = (cnt > 0 && s_den > 0.f) ? 1.f / s_den : 0.f;

    float rl = 0.f;
    for (int i = lo + w; i < hi; i += 8) {
        float a = ebuf[i - lo] * invden;
        rl += a * g_out[(size_t)i * DIM + lane];
    }
    rpart[w][lane] = rl;
    __syncthreads();
    if (w == 0) {
        float r = 0.f;
#pragma unroll
        for (int q = 0; q < 8; q++) r += rpart[q][lane];
        g_qstar[b * 2 * DIM + 32 + lane] = r;
        g_qstar[b * 2 * DIM + lane] = sqh[lane];
    }
}

__global__ void k_final(const float* __restrict__ w1,
                        const float* __restrict__ b1,
                        const float* __restrict__ w2,
                        const float* __restrict__ b2,
                        float* __restrict__ yout) {
    int b = blockIdx.x;
    int j = threadIdx.x;
    float hj = __ldg(&b1[j]);
#pragma unroll
    for (int t = 0; t < 2 * DIM; t++) hj += g_qstar[b * 2 * DIM + t] * __ldg(&w1[t * DIM + j]);
    hj = hj > 0.f ? hj : 0.f;
    float v = hj * __ldg(&w2[j]);
#pragma unroll
    for (int off = 16; off; off >>= 1) v += __shfl_xor_sync(0xffffffffu, v, off);
    if (j == 0) yout[b] = v + __ldg(&b2[0]);
}

// ---------------- launch ----------------
extern "C" void kernel_launch(void* const* d_in, const int* in_sizes, int n_in,
                              void* d_out, int out_size) {
    const float* x       = (const float*)d_in[0];
    const float* ea      = (const float*)d_in[1];
    const float* lin0w   = (const float*)d_in[2];
    const float* lin0b   = (const float*)d_in[3];
    const float* ennw1   = (const float*)d_in[4];
    const float* ennb1   = (const float*)d_in[5];
    const float* ennw2   = (const float*)d_in[6];
    const float* ennb2   = (const float*)d_in[7];
    const float* rootw   = (const float*)d_in[8];
    const float* convb   = (const float*)d_in[9];
    const float* gruwih  = (const float*)d_in[10];
    const float* gruwhh  = (const float*)d_in[11];
    const float* grubih  = (const float*)d_in[12];
    const float* grubhh  = (const float*)d_in[13];
    const float* s2swih  = (const float*)d_in[14];
    const float* s2swhh  = (const float*)d_in[15];
    const float* s2sbih  = (const float*)d_in[16];
    const float* s2sbhh  = (const float*)d_in[17];
    const float* lin1w   = (const float*)d_in[18];
    const float* lin1b   = (const float*)d_in[19];
    const float* lin2w   = (const float*)d_in[20];
    const float* lin2b   = (const float*)d_in[21];
    const int*   ei      = (const int*)d_in[22];
    const int*   batch   = (const int*)d_in[23];
    float* yout = (float*)d_out;

    k_zero_cnt<<<(NN + 1023) / 1024, 1024>>>();
    k_init_nodes<<<(NN * DIM + 255) / 256, 256>>>(x, lin0w, lin0b);
    k_edge_hidden<<<(EE * HID + 255) / 256, 256>>>(ea, ennw1, ennb1);
    k_count<<<(EE + 255) / 256, 256>>>(ei);
    k_scan<<<1, 1024>>>();
    k_fill<<<(EE + 255) / 256, 256>>>(ei);
    k_gptr<<<1, 128>>>(batch);

    for (int it = 0; it < NMP; it++) {
        k_scatter<<<NN, 128>>>(ei);
        k_gemm<<<NN / 64, 256>>>(ennw2);
        k_update<<<NN / 8, 256>>>(ennb2, rootw, convb, gruwih, gruwhh, grubih, grubhh);
    }

    k_zero_s2s<<<8, 1024>>>();
    for (int s = 0; s < S2S; s++) {
        k_lstm<<<BG, 128>>>(s2swih, s2swhh, s2sbih, s2sbhh);
        k_attend<<<BG, 256>>>();
    }
    k_final<<<BG, 32>>>(lin1w, lin1b, lin2w, lin2b, yout);
}

// round 5
// speedup vs baseline: 2.5132x; 2.5132x over previous
#include <cuda_runtime.h>
#include <math.h>

#define NN 8192
#define EE 131072
#define DIM 32
#define HID 128
#define BG 64
#define NMP 3
#define S2S 3
#define KDIM 4096   // HID*DIM

typedef unsigned long long ull;

__device__ __forceinline__ ull pk2(float lo, float hi) {
    ull r; asm("mov.b64 %0,{%1,%2};" : "=l"(r) : "f"(lo), "f"(hi)); return r;
}
__device__ __forceinline__ float2 upk2(ull v) {
    float2 r; asm("mov.b64 {%0,%1},%2;" : "=f"(r.x), "=f"(r.y) : "l"(v)); return r;
}
__device__ __forceinline__ ull ffma2(ull a, ull b, ull c) {
    ull d; asm("fma.rn.f32x2 %0,%1,%2,%3;" : "=l"(d) : "l"(a), "l"(b), "l"(c)); return d;
}
__device__ __forceinline__ ull add2(ull a, ull b) {
    ull d; asm("add.rn.f32x2 %0,%1,%2;" : "=l"(d) : "l"(a), "l"(b)); return d;
}

// ---------------- scratch (device globals; no allocation) ----------------
__device__ float g_out[NN * DIM];            // node features / GRU hidden
__device__ float g_V[(size_t)NN * KDIM];     // V[s][k][o] = sum_d out[s][d] W2[k][d*32+o]
__device__ float g_agg[NN * DIM];            // atomic-accumulated messages (by dst)
__device__ int   g_cnt[NN];                  // out-degree (src) counts
__device__ int   g_dcnt[NN];                 // in-degree (dst) counts
__device__ int   g_rowptr[NN + 1];           // CSR by src
__device__ int   g_woff[NN];
__device__ int   g_eids[EE];
__device__ float g_deg[NN];                  // max(in-degree,1)
__device__ int   g_gptr[BG + 1];
__device__ float g_qh[BG * DIM];
__device__ float g_qc[BG * DIM];
__device__ float g_qstar[BG * 2 * DIM];

__device__ __forceinline__ float sigm(float x) { return 1.0f / (1.0f + expf(-x)); }

// ---------------- setup ----------------
__global__ void k_zero_cnt() {
    int i = blockIdx.x * blockDim.x + threadIdx.x;
    if (i < NN) { g_cnt[i] = 0; g_dcnt[i] = 0; }
}

__global__ void k_zero_agg() {
    int i = blockIdx.x * blockDim.x + threadIdx.x;
    if (i < NN * DIM) g_agg[i] = 0.f;
}

__global__ void k_zero_s2s() {
    int i = blockIdx.x * blockDim.x + threadIdx.x;
    if (i < BG * DIM) { g_qh[i] = 0.f; g_qc[i] = 0.f; }
    if (i < BG * 2 * DIM) g_qstar[i] = 0.f;
}

__global__ void k_init_nodes(const float* __restrict__ x,
                             const float* __restrict__ w0,
                             const float* __restrict__ b0) {
    int idx = blockIdx.x * blockDim.x + threadIdx.x;
    if (idx >= NN * DIM) return;
    int n = idx >> 5, j = idx & 31;
    float v = x[n] * w0[j] + b0[j];
    g_out[idx] = v > 0.f ? v : 0.f;
}

__global__ void k_count(const int* __restrict__ ei) {
    int e = blockIdx.x * blockDim.x + threadIdx.x;
    if (e < EE) {
        atomicAdd(&g_cnt[ei[e]], 1);          // src (CSR grouping)
        atomicAdd(&g_dcnt[ei[EE + e]], 1);    // dst (degree for mean)
    }
}

// single-block exclusive scan of src counts -> rowptr, woff
__global__ void k_scan() {
    __shared__ int tot[1024];
    int t = threadIdx.x;
    int base = t * 8;
    int v[8]; int s = 0;
#pragma unroll
    for (int i = 0; i < 8; i++) { v[i] = g_cnt[base + i]; s += v[i]; }
    tot[t] = s;
    __syncthreads();
    for (int d = 1; d < 1024; d <<= 1) {
        int add = (t >= d) ? tot[t - d] : 0;
        __syncthreads();
        tot[t] += add;
        __syncthreads();
    }
    int run = tot[t] - s;
#pragma unroll
    for (int i = 0; i < 8; i++) {
        g_rowptr[base + i] = run;
        g_woff[base + i] = run;
        run += v[i];
    }
    if (t == 1023) g_rowptr[NN] = run;
}

__global__ void k_deg() {
    int i = blockIdx.x * blockDim.x + threadIdx.x;
    if (i < NN) g_deg[i] = (float)(g_dcnt[i] > 0 ? g_dcnt[i] : 1);
}

__global__ void k_fill(const int* __restrict__ ei) {
    int e = blockIdx.x * blockDim.x + threadIdx.x;
    if (e >= EE) return;
    int src = ei[e];
    int pos = atomicAdd(&g_woff[src], 1);
    g_eids[pos] = e;
}

__global__ void k_gptr(const int* __restrict__ batch) {
    int b = threadIdx.x;
    if (b > BG) return;
    int lo = 0, hi = NN;
    while (lo < hi) {
        int mid = (lo + hi) >> 1;
        if (batch[mid] < b) lo = mid + 1; else hi = mid;
    }
    g_gptr[b] = lo;
}

// ---------------- V GEMM: V[N,4096] = out[N,32] @ B[32,4096] ----------------
// B[d][r] = w2[k*1024 + d*32 + o], r = k*32+o.  K=32 (single pass).
// grid 4096 = 128 node-tiles (fast) x 32 r-chunks; block 256.
// thread: w=tid>>5 -> nodes {w+8j}, l=tid&31 -> r-quad rbase+4l.
__global__ void k_vgemm(const float* __restrict__ w2) {
    __shared__ float At[32][73];    // [d][n]  (73: conflict-free)
    __shared__ float Bs[32][132];   // [d][rr] (132: keeps 16B align, cf-free)
    int tid = threadIdx.x;
    int ntile = blockIdx.x & 127;
    int rchunk = blockIdx.x >> 7;
    int rbase = rchunk * 128;

#pragma unroll
    for (int i = 0; i < 8; i++) {
        int s = i * 256 + tid;
        int n = s >> 5, d = s & 31;
        At[d][n] = g_out[(ntile * 64 + n) * DIM + d];
    }
#pragma unroll
    for (int i = 0; i < 16; i++) {
        int s = i * 256 + tid;
        int d = s >> 7, rr = s & 127;
        int k = (rbase + rr) >> 5, o = rr & 31;
        Bs[d][rr] = w2[(size_t)k * 1024 + d * 32 + o];
    }
    __syncthreads();

    int w = tid >> 5, l = tid & 31;
    ull acc0[8], acc1[8];
#pragma unroll
    for (int j = 0; j < 8; j++) { acc0[j] = 0; acc1[j] = 0; }

#pragma unroll 8
    for (int d = 0; d < 32; d++) {
        const ull* bp = (const ull*)&Bs[d][4 * l];
        ull b01 = bp[0], b23 = bp[1];
#pragma unroll
        for (int j = 0; j < 8; j++) {
            float a = At[d][w + 8 * j];
            ull ap = pk2(a, a);
            acc0[j] = ffma2(ap, b01, acc0[j]);
            acc1[j] = ffma2(ap, b23, acc1[j]);
        }
    }
#pragma unroll
    for (int j = 0; j < 8; j++) {
        int n = ntile * 64 + w + 8 * j;
        float2 lo2 = upk2(acc0[j]);
        float2 hi2 = upk2(acc1[j]);
        float4 v = make_float4(lo2.x, lo2.y, hi2.x, hi2.y);
        *(float4*)&g_V[(size_t)n * KDIM + rbase + 4 * l] = v;
    }
}

// ---------------- edge contraction + scatter ----------------
// one block (128 thr) per SRC node s. V[s] slice held in registers (packed).
// thread (kq=t>>5, o=t&31): owns k in [kq*32, kq*32+32), column o.
// per edge-pair (packed f32x2): msg_e[o] = sum_k h_e[k]*V[s][k][o] + ub[o]
// then REDG atomicAdd into g_agg[dst*32+o].
__global__ void k_edges(const int* __restrict__ ei, const float* __restrict__ ea,
                        const float* __restrict__ w1, const float* __restrict__ b1,
                        const float* __restrict__ b2) {
    __shared__ float su[DIM];
    __shared__ float2 sea[8];
    __shared__ int sdst[8];
    __shared__ ull sh[4][HID];
    __shared__ ull red[16 * 33];
    int s = blockIdx.x;
    int lo = g_rowptr[s], hi = g_rowptr[s + 1];
    if (lo >= hi) return;
    int t = threadIdx.x;
    int kq = t >> 5, o = t & 31;

    float w1c0 = __ldg(&w1[t]), w1c1 = __ldg(&w1[HID + t]), b1c = __ldg(&b1[t]);
    if (t < DIM) su[t] = g_out[s * DIM + t];
    __syncthreads();

    float ub = 0.f;
#pragma unroll
    for (int d = 0; d < DIM; d++) ub += su[d] * __ldg(&b2[d * DIM + o]);

    ull vp[32];
    const float* Vs = g_V + (size_t)s * KDIM + kq * 32 * 32 + o;
#pragma unroll
    for (int kk = 0; kk < 32; kk++) {
        float v = Vs[kk * 32];
        vp[kk] = pk2(v, v);
    }

    for (int base = lo; base < hi; base += 8) {
        int m = hi - base; if (m > 8) m = 8;
        __syncthreads();
        if (t < m) {
            int e = g_eids[base + t];
            sea[t] = *(const float2*)&ea[2 * e];
            sdst[t] = ei[EE + e];
        }
        __syncthreads();
#pragma unroll
        for (int p = 0; p < 4; p++) {
            float h0 = 0.f, h1 = 0.f;
            if (2 * p < m) {
                float v = sea[2 * p].x * w1c0 + sea[2 * p].y * w1c1 + b1c;
                h0 = v > 0.f ? v : 0.f;
            }
            if (2 * p + 1 < m) {
                float v = sea[2 * p + 1].x * w1c0 + sea[2 * p + 1].y * w1c1 + b1c;
                h1 = v > 0.f ? v : 0.f;
            }
            sh[p][t] = pk2(h0, h1);
        }
        __syncthreads();
#pragma unroll
        for (int p = 0; p < 4; p++) {
            ull acc = 0;
            const ull* shp = &sh[p][kq * 32];
#pragma unroll
            for (int kk = 0; kk < 32; kk++) acc = ffma2(shp[kk], vp[kk], acc);
            red[(p * 4 + kq) * 33 + o] = acc;
        }
        __syncthreads();
        {
            int p = kq;  // thread (p, o) finalizes edge pair p
            ull sum = add2(add2(red[(p * 4 + 0) * 33 + o], red[(p * 4 + 1) * 33 + o]),
                           add2(red[(p * 4 + 2) * 33 + o], red[(p * 4 + 3) * 33 + o]));
            float2 ms = upk2(sum);
            if (2 * p < m)     atomicAdd(&g_agg[sdst[2 * p] * DIM + o], ms.x + ub);
            if (2 * p + 1 < m) atomicAdd(&g_agg[sdst[2 * p + 1] * DIM + o], ms.y + ub);
        }
    }
}

// ---------------- node update: mean + root + GRU ----------------
__global__ void k_update(const float* __restrict__ rootw,
                         const float* __restrict__ convb,
                         const float* __restrict__ wih,
                         const float* __restrict__ whh,
                         const float* __restrict__ bih,
                         const float* __restrict__ bhh) {
    __shared__ float Msm[8][DIM];
    int n = blockIdx.x * 8 + (threadIdx.x >> 5);
    int o = threadIdx.x & 31;
    int nl = threadIdx.x >> 5;

    float agg = g_agg[n * DIM + o] / g_deg[n];
    float mo = agg + __ldg(&convb[o]);
#pragma unroll
    for (int d = 0; d < DIM; d++) mo += g_out[n * DIM + d] * __ldg(&rootw[d * DIM + o]);
    mo = mo > 0.f ? mo : 0.f;
    Msm[nl][o] = mo;
    __syncthreads();

    float ir = __ldg(&bih[o]), iz = __ldg(&bih[32 + o]), inn = __ldg(&bih[64 + o]);
    float hr = __ldg(&bhh[o]), hz = __ldg(&bhh[32 + o]), hn = __ldg(&bhh[64 + o]);
#pragma unroll
    for (int d = 0; d < DIM; d++) {
        float md = Msm[nl][d];
        float hd = g_out[n * DIM + d];
        ir += md * __ldg(&wih[d * 96 + o]);
        iz += md * __ldg(&wih[d * 96 + 32 + o]);
        inn += md * __ldg(&wih[d * 96 + 64 + o]);
        hr += hd * __ldg(&whh[d * 96 + o]);
        hz += hd * __ldg(&whh[d * 96 + 32 + o]);
        hn += hd * __ldg(&whh[d * 96 + 64 + o]);
    }
    float r = sigm(ir + hr);
    float z = sigm(iz + hz);
    float nv = tanhf(inn + r * hn);
    float hold = g_out[n * DIM + o];
    float hnew = (1.f - z) * nv + z * hold;
    __syncwarp();
    g_out[n * DIM + o] = hnew;
}

// ---------------- Set2Set ----------------
__global__ void k_lstm(const float* __restrict__ wih,
                       const float* __restrict__ whh,
                       const float* __restrict__ bih,
                       const float* __restrict__ bhh) {
    __shared__ float gs[128];
    int b = blockIdx.x;
    int j = threadIdx.x;
    float g = __ldg(&bih[j]) + __ldg(&bhh[j]);
#pragma unroll
    for (int t = 0; t < 2 * DIM; t++) g += g_qstar[b * 2 * DIM + t] * __ldg(&wih[t * 128 + j]);
#pragma unroll
    for (int t = 0; t < DIM; t++) g += g_qh[b * DIM + t] * __ldg(&whh[t * 128 + j]);
    gs[j] = g;
    __syncthreads();
    if (j < 32) {
        float i_ = gs[j], f_ = gs[32 + j], gg = gs[64 + j], oo = gs[96 + j];
        float qc = sigm(f_) * g_qc[b * DIM + j] + sigm(i_) * tanhf(gg);
        g_qc[b * DIM + j] = qc;
        g_qh[b * DIM + j] = sigm(oo) * tanhf(qc);
    }
}

__global__ void k_attend() {
    __shared__ float sqh[32];
    __shared__ float ebuf[4096];
    __shared__ float wred[8];
    __shared__ float rpart[8][32];
    __shared__ float s_bmax, s_den;
    int b = blockIdx.x;
    int tid = threadIdx.x;
    int w = tid >> 5, lane = tid & 31;
    int lo = g_gptr[b], hi = g_gptr[b + 1];
    int cnt = hi - lo;
    if (tid < 32) sqh[tid] = g_qh[b * DIM + tid];
    __syncthreads();

    float mymax = -1e30f;
    for (int i = lo + w; i < hi; i += 8) {
        float v = g_out[(size_t)i * DIM + lane] * sqh[lane];
#pragma unroll
        for (int off = 16; off; off >>= 1) v += __shfl_xor_sync(0xffffffffu, v, off);
        if (lane == 0) ebuf[i - lo] = v;
        mymax = fmaxf(mymax, v);
    }
    if (lane == 0) wred[w] = mymax;
    __syncthreads();
    if (tid == 0) {
        float m = -1e30f;
        for (int q = 0; q < 8; q++) m = fmaxf(m, wred[q]);
        s_bmax = m;
    }
    __syncthreads();
    float bm = s_bmax;

    float s = 0.f;
    for (int idx = tid; idx < cnt; idx += 256) {
        float ev = expf(ebuf[idx] - bm);
        ebuf[idx] = ev;
        s += ev;
    }
#pragma unroll
    for (int off = 16; off; off >>= 1) s += __shfl_xor_sync(0xffffffffu, s, off);
    if (lane == 0) wred[w] = s;
    __syncthreads();
    if (tid == 0) {
        float t = 0.f;
        for (int q = 0; q < 8; q++) t += wred[q];
        s_den = t;
    }
    __syncthreads();
    float invden = (cnt > 0 && s_den > 0.f) ? 1.f / s_den : 0.f;

    float rl = 0.f;
    for (int i = lo + w; i < hi; i += 8) {
        float a = ebuf[i - lo] * invden;
        rl += a * g_out[(size_t)i * DIM + lane];
    }
    rpart[w][lane] = rl;
    __syncthreads();
    if (w == 0) {
        float r = 0.f;
#pragma unroll
        for (int q = 0; q < 8; q++) r += rpart[q][lane];
        g_qstar[b * 2 * DIM + 32 + lane] = r;
        g_qstar[b * 2 * DIM + lane] = sqh[lane];
    }
}

__global__ void k_final(const float* __restrict__ w1,
                        const float* __restrict__ b1,
                        const float* __restrict__ w2,
                        const float* __restrict__ b2,
                        float* __restrict__ yout) {
    int b = blockIdx.x;
    int j = threadIdx.x;
    float hj = __ldg(&b1[j]);
#pragma unroll
    for (int t = 0; t < 2 * DIM; t++) hj += g_qstar[b * 2 * DIM + t] * __ldg(&w1[t * DIM + j]);
    hj = hj > 0.f ? hj : 0.f;
    float v = hj * __ldg(&w2[j]);
#pragma unroll
    for (int off = 16; off; off >>= 1) v += __shfl_xor_sync(0xffffffffu, v, off);
    if (j == 0) yout[b] = v + __ldg(&b2[0]);
}

// ---------------- launch ----------------
extern "C" void kernel_launch(void* const* d_in, const int* in_sizes, int n_in,
                              void* d_out, int out_size) {
    const float* x       = (const float*)d_in[0];
    const float* ea      = (const float*)d_in[1];
    const float* lin0w   = (const float*)d_in[2];
    const float* lin0b   = (const float*)d_in[3];
    const float* ennw1   = (const float*)d_in[4];
    const float* ennb1   = (const float*)d_in[5];
    const float* ennw2   = (const float*)d_in[6];
    const float* ennb2   = (const float*)d_in[7];
    const float* rootw   = (const float*)d_in[8];
    const float* convb   = (const float*)d_in[9];
    const float* gruwih  = (const float*)d_in[10];
    const float* gruwhh  = (const float*)d_in[11];
    const float* grubih  = (const float*)d_in[12];
    const float* grubhh  = (const float*)d_in[13];
    const float* s2swih  = (const float*)d_in[14];
    const float* s2swhh  = (const float*)d_in[15];
    const float* s2sbih  = (const float*)d_in[16];
    const float* s2sbhh  = (const float*)d_in[17];
    const float* lin1w   = (const float*)d_in[18];
    const float* lin1b   = (const float*)d_in[19];
    const float* lin2w   = (const float*)d_in[20];
    const float* lin2b   = (const float*)d_in[21];
    const int*   ei      = (const int*)d_in[22];
    const int*   batch   = (const int*)d_in[23];
    float* yout = (float*)d_out;

    k_zero_cnt<<<(NN + 1023) / 1024, 1024>>>();
    k_init_nodes<<<(NN * DIM + 255) / 256, 256>>>(x, lin0w, lin0b);
    k_count<<<(EE + 255) / 256, 256>>>(ei);
    k_scan<<<1, 1024>>>();
    k_deg<<<(NN + 1023) / 1024, 1024>>>();
    k_fill<<<(EE + 255) / 256, 256>>>(ei);
    k_gptr<<<1, 128>>>(batch);

    for (int it = 0; it < NMP; it++) {
        k_vgemm<<<4096, 256>>>(ennw2);
        k_zero_agg<<<(NN * DIM + 1023) / 1024, 1024>>>();
        k_edges<<<NN, 128>>>(ei, ea, ennw1, ennb1, ennb2);
        k_update<<<NN / 8, 256>>>(rootw, convb, gruwih, gruwhh, grubih, grubhh);
    }

    k_zero_s2s<<<8, 1024>>>();
    for (int s = 0; s < S2S; s++) {
        k_lstm<<<BG, 128>>>(s2swih, s2swhh, s2sbih, s2sbhh);
        k_attend<<<BG, 256>>>();
    }
    k_final<<<BG, 32>>>(lin1w, lin1b, lin2w, lin2b, yout);
}